// round 15
// baseline (speedup 1.0000x reference)
#include <cuda_runtime.h>
#include <cuda_fp16.h>
#include <math.h>
#include <stdint.h>

// ---------------- problem constants ----------------
#define BB   8
#define NN   1024
#define IND  64
#define HIDD 96
#define NEG  0.2f

// ---------------- scratch (device globals) ----------------
__device__ float    g_x[6][BB * NN * HIDD];          // x0..x5
__device__ uint32_t g_hT[2][BB * HIDD * (NN / 2)];   // h transposed, fp16x2, 2 slots
__device__ float    g_es[2][BB * 3 * NN];
__device__ float    g_ed[2][BB * 3 * NN];
__device__ unsigned g_adjb[NN * NN / 32];
__device__ float    g_gates[BB * 2];
__device__ float    g_poolc[5 * 32 * BB * HIDD];     // [slot][chunk][b][col]

// ---------------- helpers ----------------
__device__ __forceinline__ float warpSum(float v) {
    #pragma unroll
    for (int o = 16; o; o >>= 1) v += __shfl_xor_sync(0xffffffffu, v, o);
    return v;
}
__device__ __forceinline__ float warpMax(float v) {
    #pragma unroll
    for (int o = 16; o; o >>= 1) v = fmaxf(v, __shfl_xor_sync(0xffffffffu, v, o));
    return v;
}
__device__ __forceinline__ float eluf(float x) { return x > 0.f ? x : expm1f(x); }
__device__ __forceinline__ float* bufsel(int id) { return g_x[id]; }

__device__ __forceinline__ uint32_t to_tf32(float f) {
    uint32_t u;
    asm("cvt.rna.tf32.f32 %0, %1;" : "=r"(u) : "f"(f));
    return u;
}
__device__ __forceinline__ void mma_tf32(float* c, uint32_t a0, uint32_t a1,
                                         uint32_t a2, uint32_t a3,
                                         uint32_t b0, uint32_t b1) {
    asm volatile(
        "mma.sync.aligned.m16n8k8.row.col.f32.tf32.tf32.f32 "
        "{%0,%1,%2,%3}, {%4,%5,%6,%7}, {%8,%9}, {%0,%1,%2,%3};"
        : "+f"(c[0]), "+f"(c[1]), "+f"(c[2]), "+f"(c[3])
        : "r"(a0), "r"(a1), "r"(a2), "r"(a3), "r"(b0), "r"(b1));
}
__device__ __forceinline__ void mma_f16(float* c, uint32_t a0, uint32_t a1,
                                        uint32_t a2, uint32_t a3,
                                        uint32_t b0, uint32_t b1) {
    asm volatile(
        "mma.sync.aligned.m16n8k16.row.col.f32.f16.f16.f32 "
        "{%0,%1,%2,%3}, {%4,%5,%6,%7}, {%8,%9}, {%0,%1,%2,%3};"
        : "+f"(c[0]), "+f"(c[1]), "+f"(c[2]), "+f"(c[3])
        : "r"(a0), "r"(a1), "r"(a2), "r"(a3), "r"(b0), "r"(b1));
}
__device__ __forceinline__ uint32_t pack_h2(float lo, float hi) {
    __half2 h = __floats2half2_rn(lo, hi);
    return *reinterpret_cast<uint32_t*>(&h);
}
__device__ __forceinline__ void ldsm4(uint32_t* r, uint32_t addr) {
    asm volatile("ldmatrix.sync.aligned.m8n8.x4.shared.b16 {%0,%1,%2,%3}, [%4];"
        : "=r"(r[0]), "=r"(r[1]), "=r"(r[2]), "=r"(r[3]) : "r"(addr));
}
__device__ __forceinline__ void barw(int id) {
    asm volatile("bar.sync %0, %1;" :: "r"(id), "r"(256) : "memory");
}

// ---------------- 1. adjacency -> bitmask ----------------
__global__ void k_adjbits(const int* __restrict__ adj) {
    int gw   = (blockIdx.x * blockDim.x + threadIdx.x) >> 5;
    int lane = threadIdx.x & 31;
    unsigned m = __ballot_sync(0xffffffffu, adj[gw * 32 + lane] > 0);
    if (lane == 0) g_adjb[gw] = m;
}

// ---------------- 2. LayerNorm + pre Linear + ELU -> x0 ----------------
__global__ __launch_bounds__(256) void k_ln_pre(
    const float* __restrict__ x, const float* __restrict__ ln_g,
    const float* __restrict__ ln_b, const float* __restrict__ W,
    const float* __restrict__ bias)
{
    __shared__ float Ws[IND * HIDD];
    __shared__ float xs[8][IND];
    int tid = threadIdx.x, warp = tid >> 5, lane = tid & 31;
    for (int i = tid; i < IND * HIDD; i += 256) Ws[i] = W[i];

    int row = blockIdx.x * 8 + warp;
    const float* xr = x + row * IND;
    float v0 = xr[lane], v1 = xr[lane + 32];
    float mu = warpSum(v0 + v1) * (1.f / IND);
    float d0 = v0 - mu, d1 = v1 - mu;
    float var = warpSum(d0 * d0 + d1 * d1) * (1.f / IND);
    float rs = rsqrtf(var + 1e-5f);
    xs[warp][lane]      = d0 * rs * ln_g[lane]      + ln_b[lane];
    xs[warp][lane + 32] = d1 * rs * ln_g[lane + 32] + ln_b[lane + 32];
    __syncthreads();

    float a0 = bias[lane], a1 = bias[lane + 32], a2 = bias[lane + 64];
    #pragma unroll
    for (int d = 0; d < IND; d++) {
        float xv = xs[warp][d];
        a0 += xv * Ws[d * HIDD + lane];
        a1 += xv * Ws[d * HIDD + lane + 32];
        a2 += xv * Ws[d * HIDD + lane + 64];
    }
    float* o = g_x[0] + row * HIDD;
    o[lane] = eluf(a0); o[lane + 32] = eluf(a1); o[lane + 64] = eluf(a2);
}

// ---------------- 3. h = mix(x) @ W via tf32 MMA; es/ed; hT(fp16) ----------------
#define GH_WS   0
#define GH_TILE 39936
#define GH_AV   (39936 + 12800)
#define GH_SMEM (GH_AV + 768)

__global__ __launch_bounds__(256) void k_gemmh(
    int ia, int ib, int ic, int mode,
    const float* __restrict__ W0, const float* __restrict__ as0,
    const float* __restrict__ ad0,
    const float* __restrict__ W1, const float* __restrict__ as1,
    const float* __restrict__ ad1, int H)
{
    extern __shared__ char dsm[];
    uint32_t* Ws_u  = (uint32_t*)(dsm + GH_WS);
    uint32_t* in_s  = (uint32_t*)(dsm + GH_TILE);
    float*    out_s = (float*)(dsm + GH_TILE);
    float*    as_s  = (float*)(dsm + GH_AV);
    float*    ad_s  = as_s + 96;

    int tid = threadIdx.x, wid = tid >> 5, lane = tid & 31;
    int g = lane >> 2, tg = lane & 3;
    int z = blockIdx.y;
    const float* W     = z ? W1 : W0;
    const float* a_src = z ? as1 : as0;
    const float* a_dst = z ? ad1 : ad0;

    int row0 = blockIdx.x * 32;
    int b = row0 >> 10, nb = row0 & (NN - 1);

    float c_a = 1.f, c_b = 0.f, c_c = 0.f;
    if (mode == 1) { float gg = g_gates[b * 2 + z]; c_a = 1.f - gg; c_b = gg; }
    else if (mode == 2) { c_b = 0.5f * g_gates[b * 2]; c_c = 0.5f * g_gates[b * 2 + 1]; }

    for (int i = tid; i < 96 * 96; i += 256) {
        int r = i / 96, c = i - r * 96;
        Ws_u[r * 104 + c] = to_tf32(W[i]);
    }
    if (tid < 96) { as_s[tid] = a_src[tid]; ad_s[tid] = a_dst[tid]; }

    const float* A  = bufsel(ia) + row0 * HIDD;
    const float* Bp = bufsel(ib) + row0 * HIDD;
    const float* Cp = bufsel(ic) + row0 * HIDD;
    for (int idx = tid; idx < 32 * 96; idx += 256) {
        int r = idx / 96, c = idx - r * 96;
        float v = c_a * A[idx];
        if (mode >= 1) v += c_b * Bp[idx];
        if (mode == 2) v += c_c * Cp[idx];
        in_s[r * 100 + c] = to_tf32(v);
    }
    __syncthreads();

    int mrow = (wid >> 2) * 16;
    int n0 = (wid & 3) * 24;
    float acc[3][4];
    #pragma unroll
    for (int nt = 0; nt < 3; nt++)
        #pragma unroll
        for (int q = 0; q < 4; q++) acc[nt][q] = 0.f;

    #pragma unroll
    for (int kt = 0; kt < 12; kt++) {
        int kl = kt * 8 + tg;
        uint32_t a0 = in_s[(mrow + g) * 100 + kl];
        uint32_t a1 = in_s[(mrow + g + 8) * 100 + kl];
        uint32_t a2 = in_s[(mrow + g) * 100 + kl + 4];
        uint32_t a3 = in_s[(mrow + g + 8) * 100 + kl + 4];
        #pragma unroll
        for (int nt = 0; nt < 3; nt++) {
            uint32_t b0 = Ws_u[kl * 104 + n0 + nt * 8 + g];
            uint32_t b1 = Ws_u[(kl + 4) * 104 + n0 + nt * 8 + g];
            mma_tf32(acc[nt], a0, a1, a2, a3, b0, b1);
        }
    }
    __syncthreads();

    #pragma unroll
    for (int nt = 0; nt < 3; nt++) {
        int col = n0 + nt * 8 + tg * 2;
        out_s[(mrow + g) * 97 + col]         = acc[nt][0];
        out_s[(mrow + g) * 97 + col + 1]     = acc[nt][1];
        out_s[(mrow + g + 8) * 97 + col]     = acc[nt][2];
        out_s[(mrow + g + 8) * 97 + col + 1] = acc[nt][3];
    }
    __syncthreads();

    uint32_t* hTu = g_hT[z] + (size_t)b * HIDD * (NN / 2);
    for (int idx = tid; idx < 96 * 16; idx += 256) {
        int d = idx >> 4, np = idx & 15;
        float lo = out_s[(2 * np) * 97 + d];
        float hi = out_s[(2 * np + 1) * 97 + d];
        hTu[(size_t)d * (NN / 2) + (nb >> 1) + np] = pack_h2(lo, hi);
    }

    #pragma unroll
    for (int rr = 0; rr < 4; rr++) {
        int r = wid * 4 + rr;
        float v0 = out_s[r * 97 + lane];
        float v1 = out_s[r * 97 + 32 + lane];
        float v2 = out_s[r * 97 + 64 + lane];
        float s0v = v0 * as_s[lane], s1v = v1 * as_s[lane + 32], s2v = v2 * as_s[lane + 64];
        float d0v = v0 * ad_s[lane], d1v = v1 * ad_s[lane + 32], d2v = v2 * ad_s[lane + 64];
        int n = nb + r;
        if (H == 1) {
            float ps = warpSum(s0v + s1v + s2v);
            float pd = warpSum(d0v + d1v + d2v);
            if (lane == 0) { g_es[z][b * NN + n] = ps; g_ed[z][b * NN + n] = pd; }
        } else {
            float s0 = warpSum(s0v), s1 = warpSum(s1v), s2 = warpSum(s2v);
            float e0 = warpSum(d0v), e1 = warpSum(d1v), e2 = warpSum(d2v);
            if (lane == 0) {
                g_es[z][(b * 3 + 0) * NN + n] = s0; g_ed[z][(b * 3 + 0) * NN + n] = e0;
                g_es[z][(b * 3 + 1) * NN + n] = s1; g_ed[z][(b * 3 + 1) * NN + n] = e1;
                g_es[z][(b * 3 + 2) * NN + n] = s2; g_ed[z][(b * 3 + 2) * NN + n] = e2;
            }
        }
    }
}

// ---------------- 4. aggregation: dual-wg, pipelined weights -> ldsm/mma ----------------
template <int D, int DW, int MINB>
__global__ __launch_bounds__(512, MINB) void k_aggf(int outid0, int H, int slot0) {
    constexpr int MT   = DW / 16;
    constexpr int ND   = D / DW;
    constexpr int NOCT = 8 / ND;
    constexpr int NI   = NOCT * 8;
    constexpr int HS   = 36;
    constexpr int HR   = NN / 64 / 2;

    __shared__ uint32_t hs[2][D * HS];
    __shared__ uint32_t edh2[2][32], e1h2[2][32], e2h2[2][32];
    __shared__ unsigned ms[2][NI][2];
    __shared__ float red[16];
    __shared__ float rsums_w[2][NI], invs[NI];
    __shared__ float pools_s[D * NOCT];
    __shared__ float buf[256][MT * 4 + 1];

    int tid = threadIdx.x;
    int wg = tid >> 8, wtid = tid & 255;
    int wwid = wtid >> 5, lane = tid & 31;
    int g = lane >> 2, tg = lane & 3;
    int oct = wwid % NOCT, dh = wwid / NOCT;
    int z = blockIdx.z;
    int outid = outid0 + z, slot = slot0 + z;
    int bh = blockIdx.y, b = bh / H, head = bh - b * H, hoff = head * D;
    int i0 = blockIdx.x * NI;
    int base_i = oct * 8;
    int i = i0 + base_i + g;

    const uint32_t* hTu = g_hT[z] + ((size_t)b * HIDD + hoff) * (NN / 2);
    const float* edp = g_ed[z] + bh * NN;

    // global ed max for this bh
    {
        float mx = -1e30f;
        if (tid < 256) {
            const float4* ed4 = (const float4*)edp;
            float4 vv = ed4[tid];
            mx = fmaxf(fmaxf(vv.x, vv.y), fmaxf(vv.z, vv.w));
        }
        mx = warpMax(mx);
        if (lane == 0) red[tid >> 5] = mx;
    }
    __syncthreads();
    float maxed = -1e30f;
    #pragma unroll
    for (int q = 0; q < 8; q++) maxed = fmaxf(maxed, red[q]);

    float es_i = g_es[z][bh * NN + i];
    __half esh = __float2half_rn(es_i);
    __half2 es2 = __halves2half2(esh, esh);
    __half2 A1_2, A2_2;
    {
        float t = es_i + maxed;
        float m = t > 0.f ? t : NEG * t;
        __half a1 = __float2half_rn(__expf(t - m));
        __half a2 = __float2half_rn(__expf(NEG * t - m));
        A1_2 = __halves2half2(a1, a1);
        A2_2 = __halves2half2(a2, a2);
    }
    const __half2 zero2 = __float2half2_rn(0.f);
    float rs = 0.f;

    float acc[MT][4];
    #pragma unroll
    for (int mt = 0; mt < MT; mt++)
        #pragma unroll
        for (int q = 0; q < 4; q++) acc[mt][q] = 0.f;

    uint32_t hs_sh = (uint32_t)__cvta_generic_to_shared(&hs[wg][0]);
    int rowa = dh * DW + ((lane >> 3) & 1) * 8 + (lane & 7);
    int colw = ((lane >> 4) & 1) * 4;
    uint32_t abase = hs_sh + (uint32_t)((rowa * HS + colw) * 4);

    for (int cc = 0; cc < HR; cc++) {
        int c = wg * HR + cc;
        barw(wg + 1);
        #pragma unroll
        for (int it = 0; it < D / 32; it++) {
            int idx4 = wtid + it * 256;
            int d = idx4 >> 3, u4 = idx4 & 7;
            uint4 v = *(const uint4*)(hTu + (size_t)d * (NN / 2) + c * 32 + u4 * 4);
            *(uint4*)&hs[wg][d * HS + u4 * 4] = v;
        }
        if (wtid < 32) {
            float2 ef = ((const float2*)(edp + c * 64))[wtid];
            edh2[wg][wtid] = pack_h2(ef.x, ef.y);
            float d0 = ef.x - maxed, d1 = ef.y - maxed;
            e1h2[wg][wtid] = pack_h2(__expf(d0), __expf(d1));
            e2h2[wg][wtid] = pack_h2(__expf(NEG * d0), __expf(NEG * d1));
        } else if (wtid >= 128 && wtid < 128 + 2 * NI) {
            int x = wtid - 128;
            ms[wg][x >> 1][x & 1] = g_adjb[(i0 + (x >> 1)) * 32 + 2 * c + (x & 1)];
        }
        barw(wg + 1);

        unsigned msw0 = ms[wg][base_i + g][0];
        unsigned msw1 = ms[wg][base_i + g][1];
        const uint32_t* edc = edh2[wg];
        const uint32_t* e1c = e1h2[wg];
        const uint32_t* e2c = e2h2[wg];

        // phase 1: all weight fragments
        uint32_t bfr[4][2];
        __half2 rsh = zero2;
        #pragma unroll
        for (int kt = 0; kt < 4; kt++) {
            unsigned msb = (kt < 2) ? msw0 : msw1;
            int p0 = kt * 8 + tg;
            int bb = (kt & 1) * 16 + 2 * tg;
            #pragma unroll
            for (int half = 0; half < 2; half++) {
                int p = p0 + half * 4;
                int bit = bb + half * 8;
                uint32_t edu = edc[p], e1u = e1c[p], e2u = e2c[p];
                __half2 t2 = __hadd2(es2, *reinterpret_cast<const __half2*>(&edu));
                __half2 p1v = __hmul2(A1_2, *reinterpret_cast<const __half2*>(&e1u));
                __half2 p2v = __hmul2(A2_2, *reinterpret_cast<const __half2*>(&e2u));
                __half2 cm = __hgt2(t2, zero2);
                __half2 w2 = __hfma2(cm, __hsub2(p1v, p2v), p2v);
                uint32_t wu = *reinterpret_cast<uint32_t*>(&w2);
                uint32_t me = ((msb >> bit) & 1u) * 0xFFFFu
                            + ((msb >> (bit + 1)) & 1u) * 0xFFFF0000u;
                wu &= me;
                rsh = __hadd2(rsh, *reinterpret_cast<const __half2*>(&wu));
                bfr[kt][half] = wu;
            }
        }
        {
            float2 rf = __half22float2(rsh);
            rs += rf.x + rf.y;
        }

        // phase 2: dense ldsm + mma
        #pragma unroll
        for (int kt = 0; kt < 4; kt++) {
            #pragma unroll
            for (int mt = 0; mt < MT; mt++) {
                uint32_t a[4];
                ldsm4(a, abase + (uint32_t)(mt * 16 * HS * 4) + kt * 32);
                mma_f16(acc[mt], a[0], a[1], a[2], a[3], bfr[kt][0], bfr[kt][1]);
            }
        }
    }

    rs += __shfl_xor_sync(0xffffffffu, rs, 1);
    rs += __shfl_xor_sync(0xffffffffu, rs, 2);
    if (dh == 0 && tg == 0) rsums_w[wg][base_i + g] = rs;

    // single-barrier accumulator merge: wg1 -> smem, wg0 adds
    if (wg == 1) {
        #pragma unroll
        for (int mt = 0; mt < MT; mt++)
            #pragma unroll
            for (int q = 0; q < 4; q++) buf[wtid][mt * 4 + q] = acc[mt][q];
    }
    __syncthreads();
    if (wg == 0) {
        #pragma unroll
        for (int mt = 0; mt < MT; mt++)
            #pragma unroll
            for (int q = 0; q < 4; q++) acc[mt][q] += buf[wtid][mt * 4 + q];
    }
    if (tid < NI) {
        float rv = rsums_w[0][tid] + rsums_w[1][tid];
        invs[tid] = (rv > 0.f) ? (1.f / rv) : 0.f;
    }
    __syncthreads();

    if (wg == 0) {
        float* outp = bufsel(outid);
        int iA = base_i + 2 * tg, iB = iA + 1;
        float invA = invs[iA], invB = invs[iB];
        size_t rowA = (size_t)(b * NN + i0 + iA) * HIDD + hoff;
        size_t rowB = rowA + HIDD;

        #pragma unroll
        for (int mt = 0; mt < MT; mt++) {
            int dlo = dh * DW + mt * 16 + g, dhi = dlo + 8;
            float o0 = eluf(acc[mt][0] * invA);
            float o1 = eluf(acc[mt][1] * invB);
            float o2 = eluf(acc[mt][2] * invA);
            float o3 = eluf(acc[mt][3] * invB);
            outp[rowA + dlo] = o0;
            outp[rowB + dlo] = o1;
            outp[rowA + dhi] = o2;
            outp[rowB + dhi] = o3;
            float plo = o0 + o1, phi = o2 + o3;
            plo += __shfl_xor_sync(0xffffffffu, plo, 1);
            plo += __shfl_xor_sync(0xffffffffu, plo, 2);
            phi += __shfl_xor_sync(0xffffffffu, phi, 1);
            phi += __shfl_xor_sync(0xffffffffu, phi, 2);
            if (tg == 0) {
                pools_s[dlo * NOCT + oct] = plo;
                pools_s[dhi * NOCT + oct] = phi;
            }
        }
    }
    __syncthreads();
    if (tid < D) {
        const float* p = pools_s + tid * NOCT;
        float s = 0.f;
        #pragma unroll
        for (int q = 0; q < NOCT; q++) s += p[q];
        g_poolc[((slot * 32 + blockIdx.x) * BB + b) * HIDD + hoff + tid] = s;
    }
}

// ---------------- 5. gate MLP ----------------
__global__ void k_gates(const float* __restrict__ w1, const float* __restrict__ b1,
                        const float* __restrict__ w2, const float* __restrict__ b2)
{
    __shared__ float pool[2 * HIDD];
    __shared__ float hid[48];
    int b = blockIdx.x, tid = threadIdx.x;
    if (tid < 192) {
        int slot = tid < 96 ? 0 : 1;
        int col = tid < 96 ? tid : tid - 96;
        float s = 0.f;
        #pragma unroll
        for (int c = 0; c < 16; c++)
            s += g_poolc[((slot * 32 + c) * BB + b) * HIDD + col];
        pool[tid] = s * (1.f / NN);
    }
    __syncthreads();
    if (tid < 48) {
        float s = b1[tid];
        #pragma unroll 4
        for (int d = 0; d < 192; d++) s += pool[d] * w1[d * 48 + tid];
        hid[tid] = eluf(s);
    }
    __syncthreads();
    if (tid < 2) {
        float s = b2[tid];
        #pragma unroll
        for (int d = 0; d < 48; d++) s += hid[d] * w2[d * 2 + tid];
        g_gates[b * 2 + tid] = 1.f / (1.f + __expf(-s));
    }
}

// ---------------- 6. final projection + output ----------------
__global__ void k_final(const float* __restrict__ proj_w, const float* __restrict__ proj_b,
                        float* __restrict__ out)
{
    __shared__ float gt[288];
    int b = blockIdx.x, tid = threadIdx.x;
    if (tid < 288) {
        int slot = 2 + tid / 96;
        int col = tid % 96;
        float s = 0.f;
        #pragma unroll 8
        for (int c = 0; c < 16; c++)
            s += g_poolc[((slot * 32 + c) * BB + b) * HIDD + col];
        gt[tid] = s * (1.f / NN);
    }
    __syncthreads();
    if (tid < 128) {
        float s = proj_b[tid];
        #pragma unroll 4
        for (int d = 0; d < 288; d++) s += gt[d] * proj_w[d * 128 + tid];
        out[b * 128 + tid] = eluf(s);
    }
    if (tid == 128) {
        out[BB * 128 + b]      = g_gates[b * 2];
        out[BB * 128 + BB + b] = g_gates[b * 2 + 1];
    }
}

// ---------------- launch ----------------
extern "C" void kernel_launch(void* const* d_in, const int* in_sizes, int n_in,
                              void* d_out, int out_size)
{
    const float* x      = (const float*)d_in[0];
    const int*   adj    = (const int*)  d_in[1];
    const float* ln_g   = (const float*)d_in[2];
    const float* ln_b   = (const float*)d_in[3];
    const float* pre_w  = (const float*)d_in[4];
    const float* pre_b  = (const float*)d_in[5];
    const float* g1_w   = (const float*)d_in[6];
    const float* g1_as  = (const float*)d_in[7];
    const float* g1_ad  = (const float*)d_in[8];
    const float* g2_w   = (const float*)d_in[9];
    const float* g2_as  = (const float*)d_in[10];
    const float* g2_ad  = (const float*)d_in[11];
    const float* g3_w   = (const float*)d_in[12];
    const float* g3_as  = (const float*)d_in[13];
    const float* g3_ad  = (const float*)d_in[14];
    const float* g4_w   = (const float*)d_in[15];
    const float* g4_as  = (const float*)d_in[16];
    const float* g4_ad  = (const float*)d_in[17];
    const float* g5_w   = (const float*)d_in[18];
    const float* g5_as  = (const float*)d_in[19];
    const float* g5_ad  = (const float*)d_in[20];
    const float* gate_w1= (const float*)d_in[21];
    const float* gate_b1= (const float*)d_in[22];
    const float* gate_w2= (const float*)d_in[23];
    const float* gate_b2= (const float*)d_in[24];
    const float* proj_w = (const float*)d_in[25];
    const float* proj_b = (const float*)d_in[26];
    float* out = (float*)d_out;

    cudaFuncSetAttribute(k_gemmh, cudaFuncAttributeMaxDynamicSharedMemorySize, GH_SMEM);

    k_adjbits<<<4096, 256>>>(adj);
    k_ln_pre<<<BB * NN / 8, 256>>>(x, ln_g, ln_b, pre_w, pre_b);

    // gat1 (x0 -> x1): H=3, D=32
    k_gemmh<<<dim3(BB * NN / 32, 1), 256, GH_SMEM>>>(
        0, 0, 0, 0, g1_w, g1_as, g1_ad, g1_w, g1_as, g1_ad, 3);
    k_aggf<32, 32, 2><<<dim3(16, BB * 3, 1), 512>>>(1, 3, 0);

    // gat2 (x1 -> x2): H=1, D=96, full-D warps, 2 blocks/SM
    k_gemmh<<<dim3(BB * NN / 32, 1), 256, GH_SMEM>>>(
        1, 0, 0, 0, g2_w, g2_as, g2_ad, g2_w, g2_as, g2_ad, 1);
    k_aggf<96, 96, 2><<<dim3(16, BB, 1), 512>>>(2, 1, 1);

    k_gates<<<BB, 256>>>(gate_w1, gate_b1, gate_w2, gate_b2);

    // gat4 + gat5 merged
    k_gemmh<<<dim3(BB * NN / 32, 2), 256, GH_SMEM>>>(
        1, 2, 0, 1, g4_w, g4_as, g4_ad, g5_w, g5_as, g5_ad, 1);
    k_aggf<96, 96, 2><<<dim3(16, BB, 2), 512>>>(4, 1, 3);

    // gat3
    k_gemmh<<<dim3(BB * NN / 32, 1), 256, GH_SMEM>>>(
        2, 4, 5, 2, g3_w, g3_as, g3_ad, g3_w, g3_as, g3_ad, 1);
    k_aggf<96, 96, 2><<<dim3(16, BB, 1), 512>>>(3, 1, 2);

    k_final<<<BB, 288>>>(proj_w, proj_b, out);
}

// round 16
// speedup vs baseline: 1.0488x; 1.0488x over previous
#include <cuda_runtime.h>
#include <cuda_fp16.h>
#include <math.h>
#include <stdint.h>

// ---------------- problem constants ----------------
#define BB   8
#define NN   1024
#define IND  64
#define HIDD 96
#define NEG  0.2f

// ---------------- scratch (device globals) ----------------
__device__ float    g_x[6][BB * NN * HIDD];          // x0..x5
__device__ uint32_t g_hT[2][BB * HIDD * (NN / 2)];   // h transposed, fp16x2, 2 slots
__device__ float    g_es[2][BB * 3 * NN];
__device__ float    g_ed[2][BB * 3 * NN];
__device__ unsigned g_adjb[NN * NN / 32];
__device__ float    g_gates[BB * 2];
__device__ float    g_poolc[5 * 32 * BB * HIDD];     // [slot][chunk][b][col]

// ---------------- helpers ----------------
__device__ __forceinline__ float warpSum(float v) {
    #pragma unroll
    for (int o = 16; o; o >>= 1) v += __shfl_xor_sync(0xffffffffu, v, o);
    return v;
}
__device__ __forceinline__ float warpMax(float v) {
    #pragma unroll
    for (int o = 16; o; o >>= 1) v = fmaxf(v, __shfl_xor_sync(0xffffffffu, v, o));
    return v;
}
__device__ __forceinline__ float eluf(float x) { return x > 0.f ? x : expm1f(x); }
__device__ __forceinline__ float* bufsel(int id) { return g_x[id]; }

__device__ __forceinline__ uint32_t to_tf32(float f) {
    uint32_t u;
    asm("cvt.rna.tf32.f32 %0, %1;" : "=r"(u) : "f"(f));
    return u;
}
__device__ __forceinline__ void mma_tf32(float* c, uint32_t a0, uint32_t a1,
                                         uint32_t a2, uint32_t a3,
                                         uint32_t b0, uint32_t b1) {
    asm volatile(
        "mma.sync.aligned.m16n8k8.row.col.f32.tf32.tf32.f32 "
        "{%0,%1,%2,%3}, {%4,%5,%6,%7}, {%8,%9}, {%0,%1,%2,%3};"
        : "+f"(c[0]), "+f"(c[1]), "+f"(c[2]), "+f"(c[3])
        : "r"(a0), "r"(a1), "r"(a2), "r"(a3), "r"(b0), "r"(b1));
}
__device__ __forceinline__ void mma_f16(float* c, uint32_t a0, uint32_t a1,
                                        uint32_t a2, uint32_t a3,
                                        uint32_t b0, uint32_t b1) {
    asm volatile(
        "mma.sync.aligned.m16n8k16.row.col.f32.f16.f16.f32 "
        "{%0,%1,%2,%3}, {%4,%5,%6,%7}, {%8,%9}, {%0,%1,%2,%3};"
        : "+f"(c[0]), "+f"(c[1]), "+f"(c[2]), "+f"(c[3])
        : "r"(a0), "r"(a1), "r"(a2), "r"(a3), "r"(b0), "r"(b1));
}
__device__ __forceinline__ uint32_t pack_h2(float lo, float hi) {
    __half2 h = __floats2half2_rn(lo, hi);
    return *reinterpret_cast<uint32_t*>(&h);
}
__device__ __forceinline__ void ldsm4(uint32_t* r, uint32_t addr) {
    asm volatile("ldmatrix.sync.aligned.m8n8.x4.shared.b16 {%0,%1,%2,%3}, [%4];"
        : "=r"(r[0]), "=r"(r[1]), "=r"(r[2]), "=r"(r[3]) : "r"(addr));
}
__device__ __forceinline__ void barw(int id) {
    asm volatile("bar.sync %0, %1;" :: "r"(id), "r"(256) : "memory");
}

// ---------------- 1. adjacency -> bitmask ----------------
__global__ void k_adjbits(const int* __restrict__ adj) {
    int gw   = (blockIdx.x * blockDim.x + threadIdx.x) >> 5;
    int lane = threadIdx.x & 31;
    unsigned m = __ballot_sync(0xffffffffu, adj[gw * 32 + lane] > 0);
    if (lane == 0) g_adjb[gw] = m;
}

// ---------------- 2. LayerNorm + pre Linear + ELU -> x0 ----------------
__global__ __launch_bounds__(256) void k_ln_pre(
    const float* __restrict__ x, const float* __restrict__ ln_g,
    const float* __restrict__ ln_b, const float* __restrict__ W,
    const float* __restrict__ bias)
{
    __shared__ float Ws[IND * HIDD];
    __shared__ float xs[8][IND];
    int tid = threadIdx.x, warp = tid >> 5, lane = tid & 31;
    for (int i = tid; i < IND * HIDD; i += 256) Ws[i] = W[i];

    int row = blockIdx.x * 8 + warp;
    const float* xr = x + row * IND;
    float v0 = xr[lane], v1 = xr[lane + 32];
    float mu = warpSum(v0 + v1) * (1.f / IND);
    float d0 = v0 - mu, d1 = v1 - mu;
    float var = warpSum(d0 * d0 + d1 * d1) * (1.f / IND);
    float rs = rsqrtf(var + 1e-5f);
    xs[warp][lane]      = d0 * rs * ln_g[lane]      + ln_b[lane];
    xs[warp][lane + 32] = d1 * rs * ln_g[lane + 32] + ln_b[lane + 32];
    __syncthreads();

    float a0 = bias[lane], a1 = bias[lane + 32], a2 = bias[lane + 64];
    #pragma unroll
    for (int d = 0; d < IND; d++) {
        float xv = xs[warp][d];
        a0 += xv * Ws[d * HIDD + lane];
        a1 += xv * Ws[d * HIDD + lane + 32];
        a2 += xv * Ws[d * HIDD + lane + 64];
    }
    float* o = g_x[0] + row * HIDD;
    o[lane] = eluf(a0); o[lane + 32] = eluf(a1); o[lane + 64] = eluf(a2);
}

// ---------------- 3. h = mix(x) @ W via tf32 MMA; es/ed; hT(fp16) ----------------
#define GH_WS   0
#define GH_TILE 39936
#define GH_AV   (39936 + 12800)
#define GH_SMEM (GH_AV + 768)

__global__ __launch_bounds__(256) void k_gemmh(
    int ia, int ib, int ic, int mode,
    const float* __restrict__ W0, const float* __restrict__ as0,
    const float* __restrict__ ad0,
    const float* __restrict__ W1, const float* __restrict__ as1,
    const float* __restrict__ ad1, int H)
{
    extern __shared__ char dsm[];
    uint32_t* Ws_u  = (uint32_t*)(dsm + GH_WS);
    uint32_t* in_s  = (uint32_t*)(dsm + GH_TILE);
    float*    out_s = (float*)(dsm + GH_TILE);
    float*    as_s  = (float*)(dsm + GH_AV);
    float*    ad_s  = as_s + 96;

    int tid = threadIdx.x, wid = tid >> 5, lane = tid & 31;
    int g = lane >> 2, tg = lane & 3;
    int z = blockIdx.y;
    const float* W     = z ? W1 : W0;
    const float* a_src = z ? as1 : as0;
    const float* a_dst = z ? ad1 : ad0;

    int row0 = blockIdx.x * 32;
    int b = row0 >> 10, nb = row0 & (NN - 1);

    float c_a = 1.f, c_b = 0.f, c_c = 0.f;
    if (mode == 1) { float gg = g_gates[b * 2 + z]; c_a = 1.f - gg; c_b = gg; }
    else if (mode == 2) { c_b = 0.5f * g_gates[b * 2]; c_c = 0.5f * g_gates[b * 2 + 1]; }

    for (int i = tid; i < 96 * 96; i += 256) {
        int r = i / 96, c = i - r * 96;
        Ws_u[r * 104 + c] = to_tf32(W[i]);
    }
    if (tid < 96) { as_s[tid] = a_src[tid]; ad_s[tid] = a_dst[tid]; }

    const float* A  = bufsel(ia) + row0 * HIDD;
    const float* Bp = bufsel(ib) + row0 * HIDD;
    const float* Cp = bufsel(ic) + row0 * HIDD;
    for (int idx = tid; idx < 32 * 96; idx += 256) {
        int r = idx / 96, c = idx - r * 96;
        float v = c_a * A[idx];
        if (mode >= 1) v += c_b * Bp[idx];
        if (mode == 2) v += c_c * Cp[idx];
        in_s[r * 100 + c] = to_tf32(v);
    }
    __syncthreads();

    int mrow = (wid >> 2) * 16;
    int n0 = (wid & 3) * 24;
    float acc[3][4];
    #pragma unroll
    for (int nt = 0; nt < 3; nt++)
        #pragma unroll
        for (int q = 0; q < 4; q++) acc[nt][q] = 0.f;

    #pragma unroll
    for (int kt = 0; kt < 12; kt++) {
        int kl = kt * 8 + tg;
        uint32_t a0 = in_s[(mrow + g) * 100 + kl];
        uint32_t a1 = in_s[(mrow + g + 8) * 100 + kl];
        uint32_t a2 = in_s[(mrow + g) * 100 + kl + 4];
        uint32_t a3 = in_s[(mrow + g + 8) * 100 + kl + 4];
        #pragma unroll
        for (int nt = 0; nt < 3; nt++) {
            uint32_t b0 = Ws_u[kl * 104 + n0 + nt * 8 + g];
            uint32_t b1 = Ws_u[(kl + 4) * 104 + n0 + nt * 8 + g];
            mma_tf32(acc[nt], a0, a1, a2, a3, b0, b1);
        }
    }
    __syncthreads();

    #pragma unroll
    for (int nt = 0; nt < 3; nt++) {
        int col = n0 + nt * 8 + tg * 2;
        out_s[(mrow + g) * 97 + col]         = acc[nt][0];
        out_s[(mrow + g) * 97 + col + 1]     = acc[nt][1];
        out_s[(mrow + g + 8) * 97 + col]     = acc[nt][2];
        out_s[(mrow + g + 8) * 97 + col + 1] = acc[nt][3];
    }
    __syncthreads();

    uint32_t* hTu = g_hT[z] + (size_t)b * HIDD * (NN / 2);
    for (int idx = tid; idx < 96 * 16; idx += 256) {
        int d = idx >> 4, np = idx & 15;
        float lo = out_s[(2 * np) * 97 + d];
        float hi = out_s[(2 * np + 1) * 97 + d];
        hTu[(size_t)d * (NN / 2) + (nb >> 1) + np] = pack_h2(lo, hi);
    }

    #pragma unroll
    for (int rr = 0; rr < 4; rr++) {
        int r = wid * 4 + rr;
        float v0 = out_s[r * 97 + lane];
        float v1 = out_s[r * 97 + 32 + lane];
        float v2 = out_s[r * 97 + 64 + lane];
        float s0v = v0 * as_s[lane], s1v = v1 * as_s[lane + 32], s2v = v2 * as_s[lane + 64];
        float d0v = v0 * ad_s[lane], d1v = v1 * ad_s[lane + 32], d2v = v2 * ad_s[lane + 64];
        int n = nb + r;
        if (H == 1) {
            float ps = warpSum(s0v + s1v + s2v);
            float pd = warpSum(d0v + d1v + d2v);
            if (lane == 0) { g_es[z][b * NN + n] = ps; g_ed[z][b * NN + n] = pd; }
        } else {
            float s0 = warpSum(s0v), s1 = warpSum(s1v), s2 = warpSum(s2v);
            float e0 = warpSum(d0v), e1 = warpSum(d1v), e2 = warpSum(d2v);
            if (lane == 0) {
                g_es[z][(b * 3 + 0) * NN + n] = s0; g_ed[z][(b * 3 + 0) * NN + n] = e0;
                g_es[z][(b * 3 + 1) * NN + n] = s1; g_ed[z][(b * 3 + 1) * NN + n] = e1;
                g_es[z][(b * 3 + 2) * NN + n] = s2; g_ed[z][(b * 3 + 2) * NN + n] = e2;
            }
        }
    }
}

// ---------------- 4. aggregation: dual-wg, pipelined weights -> ldsm/mma ----------------
template <int D, int DW, int MINB>
__global__ __launch_bounds__(512, MINB) void k_aggf(int outid0, int H, int slot0) {
    constexpr int MT   = DW / 16;
    constexpr int ND   = D / DW;
    constexpr int NOCT = 8 / ND;
    constexpr int NI   = NOCT * 8;
    constexpr int HS   = 36;
    constexpr int HR   = NN / 64 / 2;

    __shared__ uint32_t hs[2][D * HS];
    __shared__ uint32_t edh2[2][32], e1h2[2][32], e2h2[2][32];
    __shared__ unsigned ms[2][NI][2];
    __shared__ float red[16];
    __shared__ float rsums_w[2][NI], invs[NI];
    __shared__ float pools_s[D * NOCT];
    __shared__ float buf[256][MT * 4 + 1];

    int tid = threadIdx.x;
    int wg = tid >> 8, wtid = tid & 255;
    int wwid = wtid >> 5, lane = tid & 31;
    int g = lane >> 2, tg = lane & 3;
    int oct = wwid % NOCT, dh = wwid / NOCT;
    int z = blockIdx.z;
    int outid = outid0 + z, slot = slot0 + z;
    int bh = blockIdx.y, b = bh / H, head = bh - b * H, hoff = head * D;
    int i0 = blockIdx.x * NI;
    int base_i = oct * 8;
    int i = i0 + base_i + g;

    const uint32_t* hTu = g_hT[z] + ((size_t)b * HIDD + hoff) * (NN / 2);
    const float* edp = g_ed[z] + bh * NN;

    // global ed max for this bh
    {
        float mx = -1e30f;
        if (tid < 256) {
            const float4* ed4 = (const float4*)edp;
            float4 vv = ed4[tid];
            mx = fmaxf(fmaxf(vv.x, vv.y), fmaxf(vv.z, vv.w));
        }
        mx = warpMax(mx);
        if (lane == 0) red[tid >> 5] = mx;
    }
    __syncthreads();
    float maxed = -1e30f;
    #pragma unroll
    for (int q = 0; q < 8; q++) maxed = fmaxf(maxed, red[q]);

    float es_i = g_es[z][bh * NN + i];
    __half esh = __float2half_rn(es_i);
    __half2 es2 = __halves2half2(esh, esh);
    __half2 A1_2, A2_2;
    {
        float t = es_i + maxed;
        float m = t > 0.f ? t : NEG * t;
        __half a1 = __float2half_rn(__expf(t - m));
        __half a2 = __float2half_rn(__expf(NEG * t - m));
        A1_2 = __halves2half2(a1, a1);
        A2_2 = __halves2half2(a2, a2);
    }
    const __half2 zero2 = __float2half2_rn(0.f);
    float rs = 0.f;

    float acc[MT][4];
    #pragma unroll
    for (int mt = 0; mt < MT; mt++)
        #pragma unroll
        for (int q = 0; q < 4; q++) acc[mt][q] = 0.f;

    uint32_t hs_sh = (uint32_t)__cvta_generic_to_shared(&hs[wg][0]);
    int rowa = dh * DW + ((lane >> 3) & 1) * 8 + (lane & 7);
    int colw = ((lane >> 4) & 1) * 4;
    uint32_t abase = hs_sh + (uint32_t)((rowa * HS + colw) * 4);

    for (int cc = 0; cc < HR; cc++) {
        int c = wg * HR + cc;
        barw(wg + 1);
        #pragma unroll
        for (int it = 0; it < D / 32; it++) {
            int idx4 = wtid + it * 256;
            int d = idx4 >> 3, u4 = idx4 & 7;
            uint4 v = *(const uint4*)(hTu + (size_t)d * (NN / 2) + c * 32 + u4 * 4);
            *(uint4*)&hs[wg][d * HS + u4 * 4] = v;
        }
        if (wtid < 32) {
            float2 ef = ((const float2*)(edp + c * 64))[wtid];
            edh2[wg][wtid] = pack_h2(ef.x, ef.y);
            float d0 = ef.x - maxed, d1 = ef.y - maxed;
            e1h2[wg][wtid] = pack_h2(__expf(d0), __expf(d1));
            e2h2[wg][wtid] = pack_h2(__expf(NEG * d0), __expf(NEG * d1));
        } else if (wtid >= 128 && wtid < 128 + 2 * NI) {
            int x = wtid - 128;
            ms[wg][x >> 1][x & 1] = g_adjb[(i0 + (x >> 1)) * 32 + 2 * c + (x & 1)];
        }
        barw(wg + 1);

        unsigned msw0 = ms[wg][base_i + g][0];
        unsigned msw1 = ms[wg][base_i + g][1];
        const uint32_t* edc = edh2[wg];
        const uint32_t* e1c = e1h2[wg];
        const uint32_t* e2c = e2h2[wg];

        // phase 1: all weight fragments
        uint32_t bfr[4][2];
        __half2 rsh = zero2;
        #pragma unroll
        for (int kt = 0; kt < 4; kt++) {
            unsigned msb = (kt < 2) ? msw0 : msw1;
            int p0 = kt * 8 + tg;
            int bb = (kt & 1) * 16 + 2 * tg;
            #pragma unroll
            for (int half = 0; half < 2; half++) {
                int p = p0 + half * 4;
                int bit = bb + half * 8;
                uint32_t edu = edc[p], e1u = e1c[p], e2u = e2c[p];
                __half2 t2 = __hadd2(es2, *reinterpret_cast<const __half2*>(&edu));
                __half2 p1v = __hmul2(A1_2, *reinterpret_cast<const __half2*>(&e1u));
                __half2 p2v = __hmul2(A2_2, *reinterpret_cast<const __half2*>(&e2u));
                __half2 cm = __hgt2(t2, zero2);
                __half2 w2 = __hfma2(cm, __hsub2(p1v, p2v), p2v);
                uint32_t wu = *reinterpret_cast<uint32_t*>(&w2);
                uint32_t me = ((msb >> bit) & 1u) * 0xFFFFu
                            + ((msb >> (bit + 1)) & 1u) * 0xFFFF0000u;
                wu &= me;
                rsh = __hadd2(rsh, *reinterpret_cast<const __half2*>(&wu));
                bfr[kt][half] = wu;
            }
        }
        {
            float2 rf = __half22float2(rsh);
            rs += rf.x + rf.y;
        }

        // phase 2: dense ldsm + mma
        #pragma unroll
        for (int kt = 0; kt < 4; kt++) {
            #pragma unroll
            for (int mt = 0; mt < MT; mt++) {
                uint32_t a[4];
                ldsm4(a, abase + (uint32_t)(mt * 16 * HS * 4) + kt * 32);
                mma_f16(acc[mt], a[0], a[1], a[2], a[3], bfr[kt][0], bfr[kt][1]);
            }
        }
    }

    rs += __shfl_xor_sync(0xffffffffu, rs, 1);
    rs += __shfl_xor_sync(0xffffffffu, rs, 2);
    if (dh == 0 && tg == 0) rsums_w[wg][base_i + g] = rs;

    // single-barrier accumulator merge: wg1 -> smem, wg0 adds
    if (wg == 1) {
        #pragma unroll
        for (int mt = 0; mt < MT; mt++)
            #pragma unroll
            for (int q = 0; q < 4; q++) buf[wtid][mt * 4 + q] = acc[mt][q];
    }
    __syncthreads();
    if (wg == 0) {
        #pragma unroll
        for (int mt = 0; mt < MT; mt++)
            #pragma unroll
            for (int q = 0; q < 4; q++) acc[mt][q] += buf[wtid][mt * 4 + q];
    }
    if (tid < NI) {
        float rv = rsums_w[0][tid] + rsums_w[1][tid];
        invs[tid] = (rv > 0.f) ? (1.f / rv) : 0.f;
    }
    __syncthreads();

    if (wg == 0) {
        float* outp = bufsel(outid);
        int iA = base_i + 2 * tg, iB = iA + 1;
        float invA = invs[iA], invB = invs[iB];
        size_t rowA = (size_t)(b * NN + i0 + iA) * HIDD + hoff;
        size_t rowB = rowA + HIDD;

        #pragma unroll
        for (int mt = 0; mt < MT; mt++) {
            int dlo = dh * DW + mt * 16 + g, dhi = dlo + 8;
            float o0 = eluf(acc[mt][0] * invA);
            float o1 = eluf(acc[mt][1] * invB);
            float o2 = eluf(acc[mt][2] * invA);
            float o3 = eluf(acc[mt][3] * invB);
            outp[rowA + dlo] = o0;
            outp[rowB + dlo] = o1;
            outp[rowA + dhi] = o2;
            outp[rowB + dhi] = o3;
            float plo = o0 + o1, phi = o2 + o3;
            plo += __shfl_xor_sync(0xffffffffu, plo, 1);
            plo += __shfl_xor_sync(0xffffffffu, plo, 2);
            phi += __shfl_xor_sync(0xffffffffu, phi, 1);
            phi += __shfl_xor_sync(0xffffffffu, phi, 2);
            if (tg == 0) {
                pools_s[dlo * NOCT + oct] = plo;
                pools_s[dhi * NOCT + oct] = phi;
            }
        }
    }
    __syncthreads();
    if (tid < D) {
        const float* p = pools_s + tid * NOCT;
        float s = 0.f;
        #pragma unroll
        for (int q = 0; q < NOCT; q++) s += p[q];
        g_poolc[((slot * 32 + blockIdx.x) * BB + b) * HIDD + hoff + tid] = s;
    }
}

// ---------------- 5. gate MLP ----------------
__global__ void k_gates(const float* __restrict__ w1, const float* __restrict__ b1,
                        const float* __restrict__ w2, const float* __restrict__ b2)
{
    __shared__ float pool[2 * HIDD];
    __shared__ float hid[48];
    int b = blockIdx.x, tid = threadIdx.x;
    if (tid < 192) {
        int slot = tid < 96 ? 0 : 1;
        int col = tid < 96 ? tid : tid - 96;
        float s = 0.f;
        #pragma unroll
        for (int c = 0; c < 16; c++)
            s += g_poolc[((slot * 32 + c) * BB + b) * HIDD + col];
        pool[tid] = s * (1.f / NN);
    }
    __syncthreads();
    if (tid < 48) {
        float s = b1[tid];
        #pragma unroll 4
        for (int d = 0; d < 192; d++) s += pool[d] * w1[d * 48 + tid];
        hid[tid] = eluf(s);
    }
    __syncthreads();
    if (tid < 2) {
        float s = b2[tid];
        #pragma unroll
        for (int d = 0; d < 48; d++) s += hid[d] * w2[d * 2 + tid];
        g_gates[b * 2 + tid] = 1.f / (1.f + __expf(-s));
    }
}

// ---------------- 6. final projection + output ----------------
__global__ void k_final(const float* __restrict__ proj_w, const float* __restrict__ proj_b,
                        float* __restrict__ out)
{
    __shared__ float gt[288];
    int b = blockIdx.x, tid = threadIdx.x;
    if (tid < 288) {
        int slot = 2 + tid / 96;
        int col = tid % 96;
        float s = 0.f;
        #pragma unroll 8
        for (int c = 0; c < 16; c++)
            s += g_poolc[((slot * 32 + c) * BB + b) * HIDD + col];
        gt[tid] = s * (1.f / NN);
    }
    __syncthreads();
    if (tid < 128) {
        float s = proj_b[tid];
        #pragma unroll 4
        for (int d = 0; d < 288; d++) s += gt[d] * proj_w[d * 128 + tid];
        out[b * 128 + tid] = eluf(s);
    }
    if (tid == 128) {
        out[BB * 128 + b]      = g_gates[b * 2];
        out[BB * 128 + BB + b] = g_gates[b * 2 + 1];
    }
}

// ---------------- launch ----------------
extern "C" void kernel_launch(void* const* d_in, const int* in_sizes, int n_in,
                              void* d_out, int out_size)
{
    const float* x      = (const float*)d_in[0];
    const int*   adj    = (const int*)  d_in[1];
    const float* ln_g   = (const float*)d_in[2];
    const float* ln_b   = (const float*)d_in[3];
    const float* pre_w  = (const float*)d_in[4];
    const float* pre_b  = (const float*)d_in[5];
    const float* g1_w   = (const float*)d_in[6];
    const float* g1_as  = (const float*)d_in[7];
    const float* g1_ad  = (const float*)d_in[8];
    const float* g2_w   = (const float*)d_in[9];
    const float* g2_as  = (const float*)d_in[10];
    const float* g2_ad  = (const float*)d_in[11];
    const float* g3_w   = (const float*)d_in[12];
    const float* g3_as  = (const float*)d_in[13];
    const float* g3_ad  = (const float*)d_in[14];
    const float* g4_w   = (const float*)d_in[15];
    const float* g4_as  = (const float*)d_in[16];
    const float* g4_ad  = (const float*)d_in[17];
    const float* g5_w   = (const float*)d_in[18];
    const float* g5_as  = (const float*)d_in[19];
    const float* g5_ad  = (const float*)d_in[20];
    const float* gate_w1= (const float*)d_in[21];
    const float* gate_b1= (const float*)d_in[22];
    const float* gate_w2= (const float*)d_in[23];
    const float* gate_b2= (const float*)d_in[24];
    const float* proj_w = (const float*)d_in[25];
    const float* proj_b = (const float*)d_in[26];
    float* out = (float*)d_out;

    cudaFuncSetAttribute(k_gemmh, cudaFuncAttributeMaxDynamicSharedMemorySize, GH_SMEM);

    k_adjbits<<<4096, 256>>>(adj);
    k_ln_pre<<<BB * NN / 8, 256>>>(x, ln_g, ln_b, pre_w, pre_b);

    // gat1 (x0 -> x1): H=3, D=32
    k_gemmh<<<dim3(BB * NN / 32, 1), 256, GH_SMEM>>>(
        0, 0, 0, 0, g1_w, g1_as, g1_ad, g1_w, g1_as, g1_ad, 3);
    k_aggf<32, 32, 2><<<dim3(16, BB * 3, 1), 512>>>(1, 3, 0);

    // gat2 (x1 -> x2): H=1, D=96, full-D warps, unclamped regs (MINB=1)
    k_gemmh<<<dim3(BB * NN / 32, 1), 256, GH_SMEM>>>(
        1, 0, 0, 0, g2_w, g2_as, g2_ad, g2_w, g2_as, g2_ad, 1);
    k_aggf<96, 96, 1><<<dim3(16, BB, 1), 512>>>(2, 1, 1);

    k_gates<<<BB, 256>>>(gate_w1, gate_b1, gate_w2, gate_b2);

    // gat4 + gat5 merged
    k_gemmh<<<dim3(BB * NN / 32, 2), 256, GH_SMEM>>>(
        1, 2, 0, 1, g4_w, g4_as, g4_ad, g5_w, g5_as, g5_ad, 1);
    k_aggf<96, 96, 1><<<dim3(16, BB, 2), 512>>>(4, 1, 3);

    // gat3
    k_gemmh<<<dim3(BB * NN / 32, 1), 256, GH_SMEM>>>(
        2, 4, 5, 2, g3_w, g3_as, g3_ad, g3_w, g3_as, g3_ad, 1);
    k_aggf<96, 96, 1><<<dim3(16, BB, 1), 512>>>(3, 1, 2);

    k_final<<<BB, 288>>>(proj_w, proj_b, out);
}

// round 17
// speedup vs baseline: 1.0541x; 1.0051x over previous
#include <cuda_runtime.h>
#include <cuda_fp16.h>
#include <math.h>
#include <stdint.h>

// ---------------- problem constants ----------------
#define BB   8
#define NN   1024
#define IND  64
#define HIDD 96
#define NEG  0.2f

// ---------------- scratch (device globals) ----------------
__device__ float    g_x[6][BB * NN * HIDD];          // x0..x5
__device__ uint32_t g_hT[2][BB * HIDD * (NN / 2)];   // h transposed, fp16x2, 2 slots
__device__ float    g_es[2][BB * 3 * NN];
__device__ float    g_ed[2][BB * 3 * NN];
__device__ unsigned g_adjb[NN * NN / 32];
__device__ float    g_gates[BB * 2];
__device__ float    g_poolc[5 * 32 * BB * HIDD];     // [slot][chunk][b][col]

// ---------------- helpers ----------------
__device__ __forceinline__ float warpSum(float v) {
    #pragma unroll
    for (int o = 16; o; o >>= 1) v += __shfl_xor_sync(0xffffffffu, v, o);
    return v;
}
__device__ __forceinline__ float warpMax(float v) {
    #pragma unroll
    for (int o = 16; o; o >>= 1) v = fmaxf(v, __shfl_xor_sync(0xffffffffu, v, o));
    return v;
}
__device__ __forceinline__ float eluf(float x) { return x > 0.f ? x : expm1f(x); }
__device__ __forceinline__ float* bufsel(int id) { return g_x[id]; }

__device__ __forceinline__ uint32_t to_tf32(float f) {
    uint32_t u;
    asm("cvt.rna.tf32.f32 %0, %1;" : "=r"(u) : "f"(f));
    return u;
}
__device__ __forceinline__ void mma_tf32(float* c, uint32_t a0, uint32_t a1,
                                         uint32_t a2, uint32_t a3,
                                         uint32_t b0, uint32_t b1) {
    asm volatile(
        "mma.sync.aligned.m16n8k8.row.col.f32.tf32.tf32.f32 "
        "{%0,%1,%2,%3}, {%4,%5,%6,%7}, {%8,%9}, {%0,%1,%2,%3};"
        : "+f"(c[0]), "+f"(c[1]), "+f"(c[2]), "+f"(c[3])
        : "r"(a0), "r"(a1), "r"(a2), "r"(a3), "r"(b0), "r"(b1));
}
__device__ __forceinline__ void mma_f16(float* c, uint32_t a0, uint32_t a1,
                                        uint32_t a2, uint32_t a3,
                                        uint32_t b0, uint32_t b1) {
    asm volatile(
        "mma.sync.aligned.m16n8k16.row.col.f32.f16.f16.f32 "
        "{%0,%1,%2,%3}, {%4,%5,%6,%7}, {%8,%9}, {%0,%1,%2,%3};"
        : "+f"(c[0]), "+f"(c[1]), "+f"(c[2]), "+f"(c[3])
        : "r"(a0), "r"(a1), "r"(a2), "r"(a3), "r"(b0), "r"(b1));
}
__device__ __forceinline__ uint32_t pack_h2(float lo, float hi) {
    __half2 h = __floats2half2_rn(lo, hi);
    return *reinterpret_cast<uint32_t*>(&h);
}
__device__ __forceinline__ void ldsm4(uint32_t* r, uint32_t addr) {
    asm volatile("ldmatrix.sync.aligned.m8n8.x4.shared.b16 {%0,%1,%2,%3}, [%4];"
        : "=r"(r[0]), "=r"(r[1]), "=r"(r[2]), "=r"(r[3]) : "r"(addr));
}
__device__ __forceinline__ void barw(int id) {
    asm volatile("bar.sync %0, %1;" :: "r"(id), "r"(256) : "memory");
}

// ---------------- 1. merged: adjacency bitmask + LayerNorm/pre/ELU ----------------
// blocks [0, BB*NN/8): ln_pre (8 rows each); blocks [BB*NN/8, +4096): adjbits.
__global__ __launch_bounds__(256) void k_pre(
    const float* __restrict__ x, const float* __restrict__ ln_g,
    const float* __restrict__ ln_b, const float* __restrict__ W,
    const float* __restrict__ bias, const int* __restrict__ adj)
{
    __shared__ float Ws[IND * HIDD];
    __shared__ float xs[8][IND];
    int tid = threadIdx.x, warp = tid >> 5, lane = tid & 31;

    if (blockIdx.x >= BB * NN / 8) {
        int blk = blockIdx.x - BB * NN / 8;
        int gw  = (blk * 256 + tid) >> 5;
        unsigned m = __ballot_sync(0xffffffffu, adj[gw * 32 + lane] > 0);
        if (lane == 0) g_adjb[gw] = m;
        return;
    }

    for (int i = tid; i < IND * HIDD; i += 256) Ws[i] = W[i];

    int row = blockIdx.x * 8 + warp;
    const float* xr = x + row * IND;
    float v0 = xr[lane], v1 = xr[lane + 32];
    float mu = warpSum(v0 + v1) * (1.f / IND);
    float d0 = v0 - mu, d1 = v1 - mu;
    float var = warpSum(d0 * d0 + d1 * d1) * (1.f / IND);
    float rs = rsqrtf(var + 1e-5f);
    xs[warp][lane]      = d0 * rs * ln_g[lane]      + ln_b[lane];
    xs[warp][lane + 32] = d1 * rs * ln_g[lane + 32] + ln_b[lane + 32];
    __syncthreads();

    float a0 = bias[lane], a1 = bias[lane + 32], a2 = bias[lane + 64];
    #pragma unroll
    for (int d = 0; d < IND; d++) {
        float xv = xs[warp][d];
        a0 += xv * Ws[d * HIDD + lane];
        a1 += xv * Ws[d * HIDD + lane + 32];
        a2 += xv * Ws[d * HIDD + lane + 64];
    }
    float* o = g_x[0] + row * HIDD;
    o[lane] = eluf(a0); o[lane + 32] = eluf(a1); o[lane + 64] = eluf(a2);
}

// ---------------- 2. h = mix(x) @ W via tf32 MMA; es/ed; hT(fp16) ----------------
#define GH_WS   0
#define GH_TILE 39936
#define GH_AV   (39936 + 12800)
#define GH_SMEM (GH_AV + 768)

__global__ __launch_bounds__(256) void k_gemmh(
    int ia, int ib, int ic, int mode,
    const float* __restrict__ W0, const float* __restrict__ as0,
    const float* __restrict__ ad0,
    const float* __restrict__ W1, const float* __restrict__ as1,
    const float* __restrict__ ad1, int H)
{
    extern __shared__ char dsm[];
    uint32_t* Ws_u  = (uint32_t*)(dsm + GH_WS);
    uint32_t* in_s  = (uint32_t*)(dsm + GH_TILE);
    float*    out_s = (float*)(dsm + GH_TILE);
    float*    as_s  = (float*)(dsm + GH_AV);
    float*    ad_s  = as_s + 96;

    int tid = threadIdx.x, wid = tid >> 5, lane = tid & 31;
    int g = lane >> 2, tg = lane & 3;
    int z = blockIdx.y;
    const float* W     = z ? W1 : W0;
    const float* a_src = z ? as1 : as0;
    const float* a_dst = z ? ad1 : ad0;

    int row0 = blockIdx.x * 32;
    int b = row0 >> 10, nb = row0 & (NN - 1);

    float c_a = 1.f, c_b = 0.f, c_c = 0.f;
    if (mode == 1) { float gg = g_gates[b * 2 + z]; c_a = 1.f - gg; c_b = gg; }
    else if (mode == 2) { c_b = 0.5f * g_gates[b * 2]; c_c = 0.5f * g_gates[b * 2 + 1]; }

    for (int i = tid; i < 96 * 96; i += 256) {
        int r = i / 96, c = i - r * 96;
        Ws_u[r * 104 + c] = to_tf32(W[i]);
    }
    if (tid < 96) { as_s[tid] = a_src[tid]; ad_s[tid] = a_dst[tid]; }

    const float* A  = bufsel(ia) + row0 * HIDD;
    const float* Bp = bufsel(ib) + row0 * HIDD;
    const float* Cp = bufsel(ic) + row0 * HIDD;
    for (int idx = tid; idx < 32 * 96; idx += 256) {
        int r = idx / 96, c = idx - r * 96;
        float v = c_a * A[idx];
        if (mode >= 1) v += c_b * Bp[idx];
        if (mode == 2) v += c_c * Cp[idx];
        in_s[r * 100 + c] = to_tf32(v);
    }
    __syncthreads();

    int mrow = (wid >> 2) * 16;
    int n0 = (wid & 3) * 24;
    float acc[3][4];
    #pragma unroll
    for (int nt = 0; nt < 3; nt++)
        #pragma unroll
        for (int q = 0; q < 4; q++) acc[nt][q] = 0.f;

    #pragma unroll
    for (int kt = 0; kt < 12; kt++) {
        int kl = kt * 8 + tg;
        uint32_t a0 = in_s[(mrow + g) * 100 + kl];
        uint32_t a1 = in_s[(mrow + g + 8) * 100 + kl];
        uint32_t a2 = in_s[(mrow + g) * 100 + kl + 4];
        uint32_t a3 = in_s[(mrow + g + 8) * 100 + kl + 4];
        #pragma unroll
        for (int nt = 0; nt < 3; nt++) {
            uint32_t b0 = Ws_u[kl * 104 + n0 + nt * 8 + g];
            uint32_t b1 = Ws_u[(kl + 4) * 104 + n0 + nt * 8 + g];
            mma_tf32(acc[nt], a0, a1, a2, a3, b0, b1);
        }
    }
    __syncthreads();

    #pragma unroll
    for (int nt = 0; nt < 3; nt++) {
        int col = n0 + nt * 8 + tg * 2;
        out_s[(mrow + g) * 97 + col]         = acc[nt][0];
        out_s[(mrow + g) * 97 + col + 1]     = acc[nt][1];
        out_s[(mrow + g + 8) * 97 + col]     = acc[nt][2];
        out_s[(mrow + g + 8) * 97 + col + 1] = acc[nt][3];
    }
    __syncthreads();

    uint32_t* hTu = g_hT[z] + (size_t)b * HIDD * (NN / 2);
    for (int idx = tid; idx < 96 * 16; idx += 256) {
        int d = idx >> 4, np = idx & 15;
        float lo = out_s[(2 * np) * 97 + d];
        float hi = out_s[(2 * np + 1) * 97 + d];
        hTu[(size_t)d * (NN / 2) + (nb >> 1) + np] = pack_h2(lo, hi);
    }

    #pragma unroll
    for (int rr = 0; rr < 4; rr++) {
        int r = wid * 4 + rr;
        float v0 = out_s[r * 97 + lane];
        float v1 = out_s[r * 97 + 32 + lane];
        float v2 = out_s[r * 97 + 64 + lane];
        float s0v = v0 * as_s[lane], s1v = v1 * as_s[lane + 32], s2v = v2 * as_s[lane + 64];
        float d0v = v0 * ad_s[lane], d1v = v1 * ad_s[lane + 32], d2v = v2 * ad_s[lane + 64];
        int n = nb + r;
        if (H == 1) {
            float ps = warpSum(s0v + s1v + s2v);
            float pd = warpSum(d0v + d1v + d2v);
            if (lane == 0) { g_es[z][b * NN + n] = ps; g_ed[z][b * NN + n] = pd; }
        } else {
            float s0 = warpSum(s0v), s1 = warpSum(s1v), s2 = warpSum(s2v);
            float e0 = warpSum(d0v), e1 = warpSum(d1v), e2 = warpSum(d2v);
            if (lane == 0) {
                g_es[z][(b * 3 + 0) * NN + n] = s0; g_ed[z][(b * 3 + 0) * NN + n] = e0;
                g_es[z][(b * 3 + 1) * NN + n] = s1; g_ed[z][(b * 3 + 1) * NN + n] = e1;
                g_es[z][(b * 3 + 2) * NN + n] = s2; g_ed[z][(b * 3 + 2) * NN + n] = e2;
            }
        }
    }
}

// ---------------- 3. aggregation: dual-wg, packed e12, ldsm + fp16 mma ----------------
template <int D, int DW, int MINB>
__global__ __launch_bounds__(512, MINB) void k_aggf(int outid0, int H, int slot0) {
    constexpr int MT   = DW / 16;
    constexpr int ND   = D / DW;
    constexpr int NOCT = 8 / ND;
    constexpr int NI   = NOCT * 8;
    constexpr int HS   = 36;
    constexpr int HR   = NN / 64 / 2;

    __shared__ uint32_t hs[2][D * HS];
    __shared__ uint32_t edh2[2][32];
    __shared__ uint2    e12h[2][32];          // .x = e1 pair, .y = e2 pair (LDS.64)
    __shared__ unsigned ms[2][NI][2];
    __shared__ float red[16];
    __shared__ float rsums_w[2][NI], invs[NI];
    __shared__ float pools_s[D * NOCT];
    __shared__ float buf[256][MT * 4 + 1];

    int tid = threadIdx.x;
    int wg = tid >> 8, wtid = tid & 255;
    int wwid = wtid >> 5, lane = tid & 31;
    int g = lane >> 2, tg = lane & 3;
    int oct = wwid % NOCT, dh = wwid / NOCT;
    int z = blockIdx.z;
    int outid = outid0 + z, slot = slot0 + z;
    int bh = blockIdx.y, b = bh / H, head = bh - b * H, hoff = head * D;
    int i0 = blockIdx.x * NI;
    int base_i = oct * 8;
    int i = i0 + base_i + g;

    const uint32_t* hTu = g_hT[z] + ((size_t)b * HIDD + hoff) * (NN / 2);
    const float* edp = g_ed[z] + bh * NN;

    // global ed max for this bh
    {
        float mx = -1e30f;
        if (tid < 256) {
            const float4* ed4 = (const float4*)edp;
            float4 vv = ed4[tid];
            mx = fmaxf(fmaxf(vv.x, vv.y), fmaxf(vv.z, vv.w));
        }
        mx = warpMax(mx);
        if (lane == 0) red[tid >> 5] = mx;
    }
    __syncthreads();
    float maxed = -1e30f;
    #pragma unroll
    for (int q = 0; q < 8; q++) maxed = fmaxf(maxed, red[q]);

    float es_i = g_es[z][bh * NN + i];
    __half esh = __float2half_rn(es_i);
    __half2 es2 = __halves2half2(esh, esh);
    __half2 A1_2, A2_2;
    {
        float t = es_i + maxed;
        float m = t > 0.f ? t : NEG * t;
        __half a1 = __float2half_rn(__expf(t - m));
        __half a2 = __float2half_rn(__expf(NEG * t - m));
        A1_2 = __halves2half2(a1, a1);
        A2_2 = __halves2half2(a2, a2);
    }
    const __half2 zero2 = __float2half2_rn(0.f);
    float rs = 0.f;

    float acc[MT][4];
    #pragma unroll
    for (int mt = 0; mt < MT; mt++)
        #pragma unroll
        for (int q = 0; q < 4; q++) acc[mt][q] = 0.f;

    uint32_t hs_sh = (uint32_t)__cvta_generic_to_shared(&hs[wg][0]);
    int rowa = dh * DW + ((lane >> 3) & 1) * 8 + (lane & 7);
    int colw = ((lane >> 4) & 1) * 4;
    uint32_t abase = hs_sh + (uint32_t)((rowa * HS + colw) * 4);

    for (int cc = 0; cc < HR; cc++) {
        int c = wg * HR + cc;
        barw(wg + 1);
        #pragma unroll
        for (int it = 0; it < D / 32; it++) {
            int idx4 = wtid + it * 256;
            int d = idx4 >> 3, u4 = idx4 & 7;
            uint4 v = *(const uint4*)(hTu + (size_t)d * (NN / 2) + c * 32 + u4 * 4);
            *(uint4*)&hs[wg][d * HS + u4 * 4] = v;
        }
        if (wtid < 32) {
            float2 ef = ((const float2*)(edp + c * 64))[wtid];
            edh2[wg][wtid] = pack_h2(ef.x, ef.y);
            float d0 = ef.x - maxed, d1 = ef.y - maxed;
            uint2 e12;
            e12.x = pack_h2(__expf(d0), __expf(d1));
            e12.y = pack_h2(__expf(NEG * d0), __expf(NEG * d1));
            e12h[wg][wtid] = e12;
        } else if (wtid >= 128 && wtid < 128 + 2 * NI) {
            int x = wtid - 128;
            ms[wg][x >> 1][x & 1] = g_adjb[(i0 + (x >> 1)) * 32 + 2 * c + (x & 1)];
        }
        barw(wg + 1);

        unsigned msw0 = ms[wg][base_i + g][0];
        unsigned msw1 = ms[wg][base_i + g][1];
        const uint32_t* edc = edh2[wg];
        const uint2*    e12c = e12h[wg];

        // phase 1: all weight fragments
        uint32_t bfr[4][2];
        __half2 rsh = zero2;
        #pragma unroll
        for (int kt = 0; kt < 4; kt++) {
            unsigned msb = (kt < 2) ? msw0 : msw1;
            int p0 = kt * 8 + tg;
            int bb = (kt & 1) * 16 + 2 * tg;
            #pragma unroll
            for (int half = 0; half < 2; half++) {
                int p = p0 + half * 4;
                int bit = bb + half * 8;
                uint32_t edu = edc[p];
                uint2 e12 = e12c[p];
                __half2 t2 = __hadd2(es2, *reinterpret_cast<const __half2*>(&edu));
                __half2 p1v = __hmul2(A1_2, *reinterpret_cast<const __half2*>(&e12.x));
                __half2 p2v = __hmul2(A2_2, *reinterpret_cast<const __half2*>(&e12.y));
                __half2 cm = __hgt2(t2, zero2);
                __half2 w2 = __hfma2(cm, __hsub2(p1v, p2v), p2v);
                uint32_t wu = *reinterpret_cast<uint32_t*>(&w2);
                uint32_t me = ((msb >> bit) & 1u) * 0xFFFFu
                            + ((msb >> (bit + 1)) & 1u) * 0xFFFF0000u;
                wu &= me;
                rsh = __hadd2(rsh, *reinterpret_cast<const __half2*>(&wu));
                bfr[kt][half] = wu;
            }
        }
        {
            float2 rf = __half22float2(rsh);
            rs += rf.x + rf.y;
        }

        // phase 2: dense ldsm + mma
        #pragma unroll
        for (int kt = 0; kt < 4; kt++) {
            #pragma unroll
            for (int mt = 0; mt < MT; mt++) {
                uint32_t a[4];
                ldsm4(a, abase + (uint32_t)(mt * 16 * HS * 4) + kt * 32);
                mma_f16(acc[mt], a[0], a[1], a[2], a[3], bfr[kt][0], bfr[kt][1]);
            }
        }
    }

    rs += __shfl_xor_sync(0xffffffffu, rs, 1);
    rs += __shfl_xor_sync(0xffffffffu, rs, 2);
    if (dh == 0 && tg == 0) rsums_w[wg][base_i + g] = rs;

    // single-barrier accumulator merge: wg1 -> smem, wg0 adds
    if (wg == 1) {
        #pragma unroll
        for (int mt = 0; mt < MT; mt++)
            #pragma unroll
            for (int q = 0; q < 4; q++) buf[wtid][mt * 4 + q] = acc[mt][q];
    }
    __syncthreads();
    if (wg == 0) {
        #pragma unroll
        for (int mt = 0; mt < MT; mt++)
            #pragma unroll
            for (int q = 0; q < 4; q++) acc[mt][q] += buf[wtid][mt * 4 + q];
    }
    if (tid < NI) {
        float rv = rsums_w[0][tid] + rsums_w[1][tid];
        invs[tid] = (rv > 0.f) ? (1.f / rv) : 0.f;
    }
    __syncthreads();

    if (wg == 0) {
        float* outp = bufsel(outid);
        int iA = base_i + 2 * tg, iB = iA + 1;
        float invA = invs[iA], invB = invs[iB];
        size_t rowA = (size_t)(b * NN + i0 + iA) * HIDD + hoff;
        size_t rowB = rowA + HIDD;

        #pragma unroll
        for (int mt = 0; mt < MT; mt++) {
            int dlo = dh * DW + mt * 16 + g, dhi = dlo + 8;
            float o0 = eluf(acc[mt][0] * invA);
            float o1 = eluf(acc[mt][1] * invB);
            float o2 = eluf(acc[mt][2] * invA);
            float o3 = eluf(acc[mt][3] * invB);
            outp[rowA + dlo] = o0;
            outp[rowB + dlo] = o1;
            outp[rowA + dhi] = o2;
            outp[rowB + dhi] = o3;
            float plo = o0 + o1, phi = o2 + o3;
            plo += __shfl_xor_sync(0xffffffffu, plo, 1);
            plo += __shfl_xor_sync(0xffffffffu, plo, 2);
            phi += __shfl_xor_sync(0xffffffffu, phi, 1);
            phi += __shfl_xor_sync(0xffffffffu, phi, 2);
            if (tg == 0) {
                pools_s[dlo * NOCT + oct] = plo;
                pools_s[dhi * NOCT + oct] = phi;
            }
        }
    }
    __syncthreads();
    if (tid < D) {
        const float* p = pools_s + tid * NOCT;
        float s = 0.f;
        #pragma unroll
        for (int q = 0; q < NOCT; q++) s += p[q];
        g_poolc[((slot * 32 + blockIdx.x) * BB + b) * HIDD + hoff + tid] = s;
    }
}

// ---------------- 4. gate MLP ----------------
__global__ void k_gates(const float* __restrict__ w1, const float* __restrict__ b1,
                        const float* __restrict__ w2, const float* __restrict__ b2)
{
    __shared__ float pool[2 * HIDD];
    __shared__ float hid[48];
    int b = blockIdx.x, tid = threadIdx.x;
    if (tid < 192) {
        int slot = tid < 96 ? 0 : 1;
        int col = tid < 96 ? tid : tid - 96;
        float s = 0.f;
        #pragma unroll
        for (int c = 0; c < 16; c++)
            s += g_poolc[((slot * 32 + c) * BB + b) * HIDD + col];
        pool[tid] = s * (1.f / NN);
    }
    __syncthreads();
    if (tid < 48) {
        float s = b1[tid];
        #pragma unroll 4
        for (int d = 0; d < 192; d++) s += pool[d] * w1[d * 48 + tid];
        hid[tid] = eluf(s);
    }
    __syncthreads();
    if (tid < 2) {
        float s = b2[tid];
        #pragma unroll
        for (int d = 0; d < 48; d++) s += hid[d] * w2[d * 2 + tid];
        g_gates[b * 2 + tid] = 1.f / (1.f + __expf(-s));
    }
}

// ---------------- 5. final projection + output ----------------
__global__ void k_final(const float* __restrict__ proj_w, const float* __restrict__ proj_b,
                        float* __restrict__ out)
{
    __shared__ float gt[288];
    int b = blockIdx.x, tid = threadIdx.x;
    if (tid < 288) {
        int slot = 2 + tid / 96;
        int col = tid % 96;
        float s = 0.f;
        #pragma unroll 8
        for (int c = 0; c < 16; c++)
            s += g_poolc[((slot * 32 + c) * BB + b) * HIDD + col];
        gt[tid] = s * (1.f / NN);
    }
    __syncthreads();
    if (tid < 128) {
        float s = proj_b[tid];
        #pragma unroll 4
        for (int d = 0; d < 288; d++) s += gt[d] * proj_w[d * 128 + tid];
        out[b * 128 + tid] = eluf(s);
    }
    if (tid == 128) {
        out[BB * 128 + b]      = g_gates[b * 2];
        out[BB * 128 + BB + b] = g_gates[b * 2 + 1];
    }
}

// ---------------- launch ----------------
extern "C" void kernel_launch(void* const* d_in, const int* in_sizes, int n_in,
                              void* d_out, int out_size)
{
    const float* x      = (const float*)d_in[0];
    const int*   adj    = (const int*)  d_in[1];
    const float* ln_g   = (const float*)d_in[2];
    const float* ln_b   = (const float*)d_in[3];
    const float* pre_w  = (const float*)d_in[4];
    const float* pre_b  = (const float*)d_in[5];
    const float* g1_w   = (const float*)d_in[6];
    const float* g1_as  = (const float*)d_in[7];
    const float* g1_ad  = (const float*)d_in[8];
    const float* g2_w   = (const float*)d_in[9];
    const float* g2_as  = (const float*)d_in[10];
    const float* g2_ad  = (const float*)d_in[11];
    const float* g3_w   = (const float*)d_in[12];
    const float* g3_as  = (const float*)d_in[13];
    const float* g3_ad  = (const float*)d_in[14];
    const float* g4_w   = (const float*)d_in[15];
    const float* g4_as  = (const float*)d_in[16];
    const float* g4_ad  = (const float*)d_in[17];
    const float* g5_w   = (const float*)d_in[18];
    const float* g5_as  = (const float*)d_in[19];
    const float* g5_ad  = (const float*)d_in[20];
    const float* gate_w1= (const float*)d_in[21];
    const float* gate_b1= (const float*)d_in[22];
    const float* gate_w2= (const float*)d_in[23];
    const float* gate_b2= (const float*)d_in[24];
    const float* proj_w = (const float*)d_in[25];
    const float* proj_b = (const float*)d_in[26];
    float* out = (float*)d_out;

    cudaFuncSetAttribute(k_gemmh, cudaFuncAttributeMaxDynamicSharedMemorySize, GH_SMEM);

    // merged adjbits + ln_pre
    k_pre<<<BB * NN / 8 + 4096, 256>>>(x, ln_g, ln_b, pre_w, pre_b, adj);

    // gat1 (x0 -> x1): H=3, D=32
    k_gemmh<<<dim3(BB * NN / 32, 1), 256, GH_SMEM>>>(
        0, 0, 0, 0, g1_w, g1_as, g1_ad, g1_w, g1_as, g1_ad, 3);
    k_aggf<32, 32, 2><<<dim3(16, BB * 3, 1), 512>>>(1, 3, 0);

    // gat2 (x1 -> x2): H=1, D=96
    k_gemmh<<<dim3(BB * NN / 32, 1), 256, GH_SMEM>>>(
        1, 0, 0, 0, g2_w, g2_as, g2_ad, g2_w, g2_as, g2_ad, 1);
    k_aggf<96, 96, 1><<<dim3(16, BB, 1), 512>>>(2, 1, 1);

    k_gates<<<BB, 256>>>(gate_w1, gate_b1, gate_w2, gate_b2);

    // gat4 + gat5 merged
    k_gemmh<<<dim3(BB * NN / 32, 2), 256, GH_SMEM>>>(
        1, 2, 0, 1, g4_w, g4_as, g4_ad, g5_w, g5_as, g5_ad, 1);
    k_aggf<96, 96, 1><<<dim3(16, BB, 2), 512>>>(4, 1, 3);

    // gat3
    k_gemmh<<<dim3(BB * NN / 32, 1), 256, GH_SMEM>>>(
        2, 4, 5, 2, g3_w, g3_as, g3_ad, g3_w, g3_as, g3_ad, 1);
    k_aggf<96, 96, 1><<<dim3(16, BB, 1), 512>>>(3, 1, 2);

    k_final<<<BB, 288>>>(proj_w, proj_b, out);
}